// round 12
// baseline (speedup 1.0000x reference)
#include <cuda_runtime.h>
#include <stdint.h>

#define N_PTS   50000
#define B_ROWS  512
#define E_DIM   16
#define KSEL    20
#define KP1     21           // top-21; lane 0 is always "self", dropped at the end
#define TILE    128          // candidates per tile (1 per group-thread)
#define WARM    512          // warm-up candidates (per row, direct scan)
#define BTHR    256          // 2 dim-groups x 128 threads
#define QSZ     TILE
#define G_ROWS  8
#define SPLITS  6
#define NGRP    (B_ROWS / G_ROWS)        // 64
#define NBLK    (NGRP * 2 * SPLITS)      // 768
#define HID     64
#define FULLM   0xffffffffu

typedef unsigned long long ull;
typedef unsigned int uint;

__device__ float g_feats[B_ROWS][8];
__device__ float g_pval[2][NGRP][SPLITS][G_ROWS][KP1];
__device__ int   g_pidx[2][NGRP][SPLITS][G_ROWS][KP1];
__device__ int   g_flag[2][NGRP];
__device__ int   g_done = 0;

static __device__ __forceinline__ float finf() { return __int_as_float(0x7f800000); }

static __device__ __forceinline__ ull pk2(float lo, float hi) {
    ull r; asm("mov.b64 %0,{%1,%2};" : "=l"(r) : "f"(lo), "f"(hi)); return r;
}
static __device__ __forceinline__ void upk2(ull v, float& lo, float& hi) {
    asm("mov.b64 {%0,%1},%2;" : "=f"(lo), "=f"(hi) : "l"(v));
}
static __device__ __forceinline__ ull fma2(ull a, ull b, ull c) {
    ull d; asm("fma.rn.f32x2 %0,%1,%2,%3;" : "=l"(d) : "l"(a), "l"(b), "l"(c)); return d;
}
static __device__ __forceinline__ ull add2(ull a, ull b) {
    ull d; asm("add.rn.f32x2 %0,%1,%2;" : "=l"(d) : "l"(a), "l"(b)); return d;
}

// ---------------------------------------------------------------------------
// Asymmetric dim-split producer/consumer KNN.
// grid = (64 groups, 2 sets, 6 splits) = 768 blocks x 256 threads, occ 2.
// Group 0 (warps 0-3) = producer: dims 0-7; per tile computes 8-row partial
//   s-halves for its candidate, writes 32B (2 STS.128, 48B stride).
// Group 1 (warps 4-7) = consumer (lagged 1 tile): dims 8-15; sums halves,
//   gates IN REGISTERS vs cached per-row thresholds, pushes rare hits into
//   per-row queues; drains queues into 2 warp-distributed top-21 lists/warp.
// ONE __syncthreads per 128 candidates. q never touches smem.
// ---------------------------------------------------------------------------
__global__ __launch_bounds__(BTHR, 2)
void knn_kernel(const float* __restrict__ emb0, const float* __restrict__ emb1,
                const float* __restrict__ rctx0, const float* __restrict__ rctx1,
                const int* __restrict__ idx0, const int* __restrict__ idx1,
                const float* __restrict__ mean_in, const float* __restrict__ std_in,
                const float* __restrict__ W1, const float* __restrict__ b1,
                const float* __restrict__ Wm, const float* __restrict__ bm,
                const float* __restrict__ Ws, const float* __restrict__ bs,
                float* __restrict__ out, int n) {
    const int grp   = blockIdx.x;
    const int set   = blockIdx.y;
    const int split = blockIdx.z;
    const float* __restrict__ emb  = set ? emb1 : emb0;
    const float* __restrict__ rctx = set ? rctx1 : rctx0;
    const int*   __restrict__ idxp = set ? idx1 : idx0;

    const int rowbase = grp * G_ROWS;
    const int tid  = threadIdx.x;
    const int lane = tid & 31;
    const int w    = tid >> 5;          // warp 0..7
    const int g    = tid >> 7;          // dim-group 0/1
    const int lt   = tid & 127;         // candidate slot in tile

    __shared__ float pb[2][TILE][12];   // partials, 48B stride (12KB)
    __shared__ float qv[2][G_ROWS][QSZ];
    __shared__ int   qi[2][G_ROWS][QSZ];
    __shared__ int   qcnt[2][G_ROWS];
    __shared__ __align__(16) float th_sm[G_ROWS];
    __shared__ float na_sm[G_ROWS];
    __shared__ ull   lst[G_ROWS][KP1];
    __shared__ int   smflag[2];

    const int halfn = (n + SPLITS - 1) / SPLITS;
    const int jbeg  = split * halfn;
    const int jend  = min(n, jbeg + halfn);

    // ---- staging: warp w computes |a|^2 for row w ----
    {
        int si = 0;
        if (lane == 0) si = idxp[rowbase + w];
        si = __shfl_sync(FULLM, si, 0);
        float nx = 0.f;
        if (lane < 8) {
            float2 v = reinterpret_cast<const float2*>(emb + (size_t)si * E_DIM)[lane];
            nx = v.x * v.x + v.y * v.y;
        }
        nx += __shfl_xor_sync(FULLM, nx, 4);
        nx += __shfl_xor_sync(FULLM, nx, 2);
        nx += __shfl_xor_sync(FULLM, nx, 1);
        if (lane == 0) na_sm[w] = nx;
    }
    if (tid < 16) qcnt[tid >> 3][tid & 7] = 0;

    // ================= warm-up: warp w scans first WARM cands for row w =====
    {
        int si = idxp[rowbase + w];
        const ulonglong2* qp = reinterpret_cast<const ulonglong2*>(emb + (size_t)si * E_DIM);
        ulonglong2 qa4 = qp[0], qb4 = qp[1], qc4 = qp[2], qd4 = qp[3];
        // negate*2 pack
        float l, h;
        upk2(qa4.x, l, h); ull qa = pk2(-2.f*l, -2.f*h);
        upk2(qa4.y, l, h); ull qb = pk2(-2.f*l, -2.f*h);
        upk2(qb4.x, l, h); ull qc = pk2(-2.f*l, -2.f*h);
        upk2(qb4.y, l, h); ull qd = pk2(-2.f*l, -2.f*h);
        upk2(qc4.x, l, h); ull qe = pk2(-2.f*l, -2.f*h);
        upk2(qc4.y, l, h); ull qf = pk2(-2.f*l, -2.f*h);
        upk2(qd4.x, l, h); ull qg = pk2(-2.f*l, -2.f*h);
        upk2(qd4.y, l, h); ull qh = pk2(-2.f*l, -2.f*h);

        float kval = finf(), thresh = finf();
        int   kidx = -1;
#pragma unroll 1
        for (int c = 0; c < WARM / 32; c++) {
            int j = jbeg + 32 * c + lane;           // range >= WARM always
            const ulonglong2* p = reinterpret_cast<const ulonglong2*>(emb + (size_t)j * E_DIM);
            ulonglong2 x = p[0], y = p[1], z = p[2], u = p[3];
            ull nA = fma2(x.x, x.x, 0ULL), nB = fma2(x.y, x.y, 0ULL);
            nA = fma2(y.x, y.x, nA);  nB = fma2(y.y, y.y, nB);
            nA = fma2(z.x, z.x, nA);  nB = fma2(z.y, z.y, nB);
            nA = fma2(u.x, u.x, nA);  nB = fma2(u.y, u.y, nB);
            ull a = add2(nA, nB);
            a = fma2(qa, x.x, a);  a = fma2(qb, x.y, a);
            a = fma2(qc, y.x, a);  a = fma2(qd, y.y, a);
            a = fma2(qe, z.x, a);  a = fma2(qf, z.y, a);
            a = fma2(qg, u.x, a);  a = fma2(qh, u.y, a);
            float lo, hi; upk2(a, lo, hi);
            float s = lo + hi;
            uint m = __ballot_sync(FULLM, s < thresh);
            while (m) {
                int src = __ffs(m) - 1; m &= m - 1;
                float bv = __shfl_sync(FULLM, s, src);
                int   bj = jbeg + 32 * c + src;
                if (bv < thresh) {
                    float pv = __shfl_up_sync(FULLM, kval, 1);
                    int   pj = __shfl_up_sync(FULLM, kidx, 1);
                    if (lane < KP1 && bv < kval) {
                        if (lane == 0 || bv >= pv) { kval = bv; kidx = bj; }
                        else                        { kval = pv; kidx = pj; }
                    }
                    thresh = __shfl_sync(FULLM, kval, KP1 - 1);
                }
            }
        }
        if (lane < KP1)
            lst[w][lane] = (((ull)(uint)kidx) << 32) | __float_as_uint(kval);
        if (lane == 0) th_sm[w] = thresh;
    }

    // ---- q halves for all 8 rows (this group's dims), packed -2*q ----
    ull q2[G_ROWS][4];
#pragma unroll
    for (int r = 0; r < G_ROWS; r++) {
        int si = idxp[rowbase + r];
        const float4* qp = reinterpret_cast<const float4*>(emb + (size_t)si * E_DIM + 8 * g);
        float4 v0 = qp[0], v1 = qp[1];
        q2[r][0] = pk2(-2.f * v0.x, -2.f * v0.y);
        q2[r][1] = pk2(-2.f * v0.z, -2.f * v0.w);
        q2[r][2] = pk2(-2.f * v1.x, -2.f * v1.y);
        q2[r][3] = pk2(-2.f * v1.z, -2.f * v1.w);
    }
    __syncthreads();

    // ---- group1: load warm-up lists for its two rows ----
    const int w1 = w - 4;               // consumer warp index 0..3
    float kv[2], th[2];
    int   ki[2];
#pragma unroll
    for (int i = 0; i < 2; i++) { kv[i] = finf(); ki[i] = -1; th[i] = finf(); }
    if (g == 1) {
#pragma unroll
        for (int i = 0; i < 2; i++) {
            int r = 2 * w1 + i;
            if (lane < KP1) {
                ull ent = lst[r][lane];
                kv[i] = __uint_as_float((uint)ent);
                ki[i] = (int)(ent >> 32);
            }
            th[i] = __shfl_sync(FULLM, kv[i], KP1 - 1);
        }
    }

    const int base   = jbeg + WARM;
    const int ntiles = (jend - base + TILE - 1) / TILE;

    // ================= main loop: ONE barrier per tile =====================
    ull e[4];                           // this group's 32B of its candidate
    if (g == 0) {                       // producer preloads tile 0
        int j = min(base + lt, jend - 1);
        const ulonglong2* p = reinterpret_cast<const ulonglong2*>(emb + (size_t)j * E_DIM);
        e[0] = p[0].x; e[1] = p[0].y; e[2] = p[1].x; e[3] = p[1].y;
    }

    for (int t = 0; t <= ntiles; t++) {
        if (g == 0) {
            if (t < ntiles) {
                ull nA = fma2(e[0], e[0], 0ULL), nB = fma2(e[1], e[1], 0ULL);
                nA = fma2(e[2], e[2], nA);  nB = fma2(e[3], e[3], nB);
                ull nrm = add2(nA, nB);
                float part[8];
#pragma unroll
                for (int r = 0; r < G_ROWS; r++) {
                    ull a = nrm;
                    a = fma2(q2[r][0], e[0], a);
                    a = fma2(q2[r][1], e[1], a);
                    a = fma2(q2[r][2], e[2], a);
                    a = fma2(q2[r][3], e[3], a);
                    float lo, hi; upk2(a, lo, hi);
                    part[r] = lo + hi;
                }
                float4* dst = reinterpret_cast<float4*>(&pb[t & 1][lt][0]);
                dst[0] = make_float4(part[0], part[1], part[2], part[3]);
                dst[1] = make_float4(part[4], part[5], part[6], part[7]);
                if (t + 1 < ntiles) {
                    int j = min(base + (t + 1) * TILE + lt, jend - 1);
                    const ulonglong2* p = reinterpret_cast<const ulonglong2*>(emb + (size_t)j * E_DIM);
                    e[0] = p[0].x; e[1] = p[0].y; e[2] = p[1].x; e[3] = p[1].y;
                }
            }
        } else {
            // ---- drain queue parity t&1 (hits of tile t-2) ----
            const int par0 = t & 1;
#pragma unroll
            for (int i = 0; i < 2; i++) {
                int r = 2 * w1 + i;
                int m = qcnt[par0][r];
                for (int b0 = 0; b0 < m; b0 += 32) {
                    bool  act = (b0 + lane < m);
                    float bvl = act ? qv[par0][r][b0 + lane] : finf();
                    int   bjl = act ? qi[par0][r][b0 + lane] : 0;
                    uint msk = __ballot_sync(FULLM, act && bvl < th[i]);
                    while (msk) {
                        int src = __ffs(msk) - 1; msk &= msk - 1;
                        float bv = __shfl_sync(FULLM, bvl, src);
                        int   bj = __shfl_sync(FULLM, bjl, src);
                        if (bv < th[i]) {
                            float pv = __shfl_up_sync(FULLM, kv[i], 1);
                            int   pj = __shfl_up_sync(FULLM, ki[i], 1);
                            if (lane < KP1 && bv < kv[i]) {
                                if (lane == 0 || bv >= pv) { kv[i] = bv; ki[i] = bj; }
                                else                        { kv[i] = pv; ki[i] = pj; }
                            }
                            th[i] = __shfl_sync(FULLM, kv[i], KP1 - 1);
                        }
                    }
                }
                if (lane == 0) { qcnt[par0][r] = 0; th_sm[r] = th[i]; }
            }
            // ---- consume tile t-1: own half + producer half, gate, push ----
            if (t >= 1) {
                const int tp   = t - 1;
                const int par1 = tp & 1;
                float4 tA = *reinterpret_cast<const float4*>(&th_sm[0]);
                float4 tB = *reinterpret_cast<const float4*>(&th_sm[4]);
                const float thr[8] = {tA.x, tA.y, tA.z, tA.w, tB.x, tB.y, tB.z, tB.w};

                ull nA = fma2(e[0], e[0], 0ULL), nB = fma2(e[1], e[1], 0ULL);
                nA = fma2(e[2], e[2], nA);  nB = fma2(e[3], e[3], nB);
                ull nrm = add2(nA, nB);
                const float4* src4 = reinterpret_cast<const float4*>(&pb[par1][lt][0]);
                float4 pA = src4[0], pB = src4[1];
                const float po[8] = {pA.x, pA.y, pA.z, pA.w, pB.x, pB.y, pB.z, pB.w};
                const int j = base + tp * TILE + lt;
                const bool vld = (j < jend);
#pragma unroll
                for (int r = 0; r < G_ROWS; r++) {
                    ull a = nrm;
                    a = fma2(q2[r][0], e[0], a);
                    a = fma2(q2[r][1], e[1], a);
                    a = fma2(q2[r][2], e[2], a);
                    a = fma2(q2[r][3], e[3], a);
                    float lo, hi; upk2(a, lo, hi);
                    float s = lo + hi + po[r];
                    if (vld && s < thr[r]) {
                        int p = atomicAdd(&qcnt[par1][r], 1);
                        qv[par1][r][p] = s;
                        qi[par1][r][p] = j;
                    }
                }
            }
            // ---- load own e half for tile t (consumed next iteration) ----
            if (t < ntiles) {
                int j = min(base + t * TILE + lt, jend - 1);
                const ulonglong2* p = reinterpret_cast<const ulonglong2*>(
                    emb + (size_t)j * E_DIM + 8);
                e[0] = p[0].x; e[1] = p[0].y; e[2] = p[1].x; e[3] = p[1].y;
            }
        }
        __syncthreads();
    }

    // ---- final drain: hits of tile ntiles-1 in parity (ntiles-1)&1 ----
    if (g == 1) {
        const int par0 = (ntiles - 1) & 1;
#pragma unroll
        for (int i = 0; i < 2; i++) {
            int r = 2 * w1 + i;
            int m = qcnt[par0][r];
            for (int b0 = 0; b0 < m; b0 += 32) {
                bool  act = (b0 + lane < m);
                float bvl = act ? qv[par0][r][b0 + lane] : finf();
                int   bjl = act ? qi[par0][r][b0 + lane] : 0;
                uint msk = __ballot_sync(FULLM, act && bvl < th[i]);
                while (msk) {
                    int src = __ffs(msk) - 1; msk &= msk - 1;
                    float bv = __shfl_sync(FULLM, bvl, src);
                    int   bj = __shfl_sync(FULLM, bjl, src);
                    if (bv < th[i]) {
                        float pv = __shfl_up_sync(FULLM, kv[i], 1);
                        int   pj = __shfl_up_sync(FULLM, ki[i], 1);
                        if (lane < KP1 && bv < kv[i]) {
                            if (lane == 0 || bv >= pv) { kv[i] = bv; ki[i] = bj; }
                            else                        { kv[i] = pv; ki[i] = pj; }
                        }
                        th[i] = __shfl_sync(FULLM, kv[i], KP1 - 1);
                    }
                }
            }
        }
        // publish final lists
        if (lane < KP1) {
#pragma unroll
            for (int i = 0; i < 2; i++)
                lst[2 * w1 + i][lane] =
                    (((ull)(uint)ki[i]) << 32) | __float_as_uint(kv[i]);
        }
    }
    __syncthreads();

    // ---- every warp w adopts row w's list for the rendezvous ----
    float kval = finf(), thresh = finf();
    int   kidx = -1;
    if (lane < KP1) {
        ull ent = lst[w][lane];
        kval = __uint_as_float((uint)ent);
        kidx = (int)(ent >> 32);
    }
    thresh = __shfl_sync(FULLM, kval, KP1 - 1);

    auto insert = [&](float bv, int bj) {
        float pv = __shfl_up_sync(FULLM, kval, 1);
        int   pj = __shfl_up_sync(FULLM, kidx, 1);
        if (lane < KP1 && bv < kval) {
            if (lane == 0 || bv >= pv) { kval = bv; kidx = bj; }
            else                        { kval = pv; kidx = pj; }
        }
        thresh = __shfl_sync(FULLM, kval, KP1 - 1);
    };

    // ================= split rendezvous (6 partials) =================
    if (lane < KP1) {
        g_pval[set][grp][split][w][lane] = kval;
        g_pidx[set][grp][split][w][lane] = kidx;
    }
    __threadfence();
    __syncthreads();
    if (tid == 0) smflag[0] = atomicAdd(&g_flag[set][grp], 1);
    __syncthreads();

    if (smflag[0] == SPLITS - 1) {          // last arrival merges + features
        __threadfence();
#pragma unroll 1
        for (int s2 = 0; s2 < SPLITS; s2++) {
            if (s2 == split) continue;
            for (int i = 0; i < KP1; i++) {
                float bv = g_pval[set][grp][s2][w][i];
                int   bj = g_pidx[set][grp][s2][w][i];
                if (bv < thresh) insert(bv, bj);
            }
        }
        // lane 0 = "self" (s = -|a|^2, strict global min): dropped
        const int row = rowbase + w;
        const float na = na_sm[w];
        float wgt = 0.f, sel = 0.f;
        if (lane >= 1 && lane < KP1) {
            float d2  = fmaxf(kval + na, 0.f);
            float sim = sqrtf(d2) + 0.001f;
            wgt = __expf(-sim);
            sel = rctx[(size_t)row * n + kidx];
        }
        float sw = wgt, ssw = sel * wgt, ss = sel, ss2 = sel * sel;
#pragma unroll
        for (int off = 16; off; off >>= 1) {
            sw  += __shfl_xor_sync(FULLM, sw,  off);
            ssw += __shfl_xor_sync(FULLM, ssw, off);
            ss  += __shfl_xor_sync(FULLM, ss,  off);
            ss2 += __shfl_xor_sync(FULLM, ss2, off);
        }
        if (lane == 0) {
            g_feats[row][0 + set] = sw;
            g_feats[row][2 + set] = ssw / sw;
            float var = (ss2 - ss * ss / (float)KSEL) / (float)(KSEL - 1);
            g_feats[row][4 + set] = sqrtf(fmaxf(var, 0.f));
        }
        if (tid == 0) g_flag[set][grp] = 0;
    }

    // ================= global tail: MLP =================
    __threadfence();
    __syncthreads();
    if (tid == 0) smflag[1] = atomicAdd(&g_done, 1);
    __syncthreads();
    if (smflag[1] != NBLK - 1) return;
    __threadfence();

#pragma unroll
    for (int rr = 0; rr < 2; rr++) {
        int r = tid + BTHR * rr;
        float f[8];
#pragma unroll
        for (int i = 0; i < 6; i++) f[i] = g_feats[r][i];
        f[6] = mean_in[r];
        f[7] = std_in[r];
        float m = bm[0], sd = bs[0];
#pragma unroll 4
        for (int jj = 0; jj < HID; jj++) {
            float h = b1[jj];
#pragma unroll
            for (int i = 0; i < 8; i++) h = fmaf(f[i], W1[i * HID + jj], h);
            h = fmaxf(h, 0.f);
            m  = fmaf(h, Wm[jj], m);
            sd = fmaf(h, Ws[jj], sd);
        }
        out[r]          = m;
        out[B_ROWS + r] = sd;
    }
    if (tid == 0) g_done = 0;
}

// ---------------------------------------------------------------------------
extern "C" void kernel_launch(void* const* d_in, const int* in_sizes, int n_in,
                              void* d_out, int out_size) {
    const float* emb0    = (const float*)d_in[0];
    const float* emb1    = (const float*)d_in[1];
    const float* rctx0   = (const float*)d_in[2];
    const float* rctx1   = (const float*)d_in[3];
    const int*   idx0    = (const int*)  d_in[4];
    const int*   idx1    = (const int*)  d_in[5];
    const float* mean_in = (const float*)d_in[6];
    const float* std_in  = (const float*)d_in[7];
    const float* W1      = (const float*)d_in[8];
    const float* b1      = (const float*)d_in[9];
    const float* Wm      = (const float*)d_in[10];
    const float* bm      = (const float*)d_in[11];
    const float* Ws      = (const float*)d_in[12];
    const float* bs      = (const float*)d_in[13];

    int n = in_sizes[0] / E_DIM;    // 50000

    dim3 grid(NGRP, 2, SPLITS);
    knn_kernel<<<grid, BTHR>>>(emb0, emb1, rctx0, rctx1, idx0, idx1,
                               mean_in, std_in, W1, b1, Wm, bm, Ws, bs,
                               (float*)d_out, n);
}

// round 13
// speedup vs baseline: 1.2031x; 1.2031x over previous
#include <cuda_runtime.h>
#include <stdint.h>

#define N_PTS   50000
#define B_ROWS  512
#define E_DIM   16
#define KSEL    20
#define KP1     21            // top-21; lane 0 is always "self", dropped at the end
#define WARM    512           // warm-up candidates (full-dim direct scan per row)
#define BTHR    256
#define G_ROWS  8
#define SPLITS  2
#define NGRP    (B_ROWS / G_ROWS)        // 64
#define NBLK    (NGRP * 2 * SPLITS)      // 256
#define HID     64
#define FULLM   0xffffffffu

typedef unsigned long long ull;
typedef unsigned int uint;

__device__ float g_feats[B_ROWS][8];
__device__ float g_pval[2][NGRP][SPLITS][G_ROWS][KP1];
__device__ int   g_pidx[2][NGRP][SPLITS][G_ROWS][KP1];
__device__ int   g_flag[2][NGRP];
__device__ int   g_done = 0;

static __device__ __forceinline__ float finf() { return __int_as_float(0x7f800000); }

static __device__ __forceinline__ ull pk2(float lo, float hi) {
    ull r; asm("mov.b64 %0,{%1,%2};" : "=l"(r) : "f"(lo), "f"(hi)); return r;
}
static __device__ __forceinline__ void upk2(ull v, float& lo, float& hi) {
    asm("mov.b64 {%0,%1},%2;" : "=f"(lo), "=f"(hi) : "l"(v));
}
static __device__ __forceinline__ ull fma2(ull a, ull b, ull c) {
    ull d; asm("fma.rn.f32x2 %0,%1,%2,%3;" : "=l"(d) : "l"(a), "l"(b), "l"(c)); return d;
}

// ---------------------------------------------------------------------------
// Lane-pair dim-split, barrier-free KNN.
// grid = (64 groups, 2 sets, 2 splits) = 256 blocks x 256 threads, occ 2.
// Lanes (2k,2k+1) co-own candidate k (16 cands/warp/iter); even lane holds
// dims 0-7, odd lane dims 8-15. q for 8 rows x own-half = 64 regs.
// Full s per row = partial + shfl_xor(partial,1). Selection fully
// register-resident: block-shared stale-safe thresholds gate inserts into
// 8 warp-distributed sorted top-21 lists per warp. NO main-loop barriers.
// ---------------------------------------------------------------------------
__global__ __launch_bounds__(BTHR, 2)
void knn_kernel(const float* __restrict__ emb0, const float* __restrict__ emb1,
                const float* __restrict__ rctx0, const float* __restrict__ rctx1,
                const int* __restrict__ idx0, const int* __restrict__ idx1,
                const float* __restrict__ mean_in, const float* __restrict__ std_in,
                const float* __restrict__ W1, const float* __restrict__ b1,
                const float* __restrict__ Wm, const float* __restrict__ bm,
                const float* __restrict__ Ws, const float* __restrict__ bs,
                float* __restrict__ out, int n) {
    const int grp   = blockIdx.x;
    const int set   = blockIdx.y;
    const int split = blockIdx.z;
    const float* __restrict__ emb  = set ? emb1 : emb0;
    const float* __restrict__ rctx = set ? rctx1 : rctx0;
    const int*   __restrict__ idxp = set ? idx1 : idx0;

    const int rowbase = grp * G_ROWS;
    const int tid  = threadIdx.x;
    const int lane = tid & 31;
    const int w    = tid >> 5;          // warp 0..7
    const int half = lane & 1;          // dim half owned by this lane
    const int k    = lane >> 1;         // candidate slot within warp (0..15)

    __shared__ float th_sm[G_ROWS];     // shared gate thresholds (stale-safe)
    __shared__ float na_sm[G_ROWS];
    __shared__ ull   lst[G_ROWS][G_ROWS][KP1];  // [warp][row][k] packed
    __shared__ int   smflag[2];

    const int halfn = (n + SPLITS - 1) / SPLITS;
    const int jbeg  = split * halfn;
    const int jend  = min(n, jbeg + halfn);

    // ---- |a|^2 per row (warp w handles row w) ----
    {
        int si = 0;
        if (lane == 0) si = idxp[rowbase + w];
        si = __shfl_sync(FULLM, si, 0);
        float nx = 0.f;
        if (lane < 8) {
            float2 v = reinterpret_cast<const float2*>(emb + (size_t)si * E_DIM)[lane];
            nx = v.x * v.x + v.y * v.y;
        }
        nx += __shfl_xor_sync(FULLM, nx, 4);
        nx += __shfl_xor_sync(FULLM, nx, 2);
        nx += __shfl_xor_sync(FULLM, nx, 1);
        if (lane == 0) na_sm[w] = nx;
    }

    // ================= warm-up: warp w full-dim scans row w ================
    float wkv = finf(), wth = finf();
    int   wki = -1;
    {
        int si = __shfl_sync(FULLM, (lane == 0) ? idxp[rowbase + w] : 0, 0);
        const ulonglong2* qp = reinterpret_cast<const ulonglong2*>(emb + (size_t)si * E_DIM);
        ulonglong2 qa4 = qp[0], qb4 = qp[1], qc4 = qp[2], qd4 = qp[3];
        float l, h;
        upk2(qa4.x, l, h); ull qa = pk2(-2.f*l, -2.f*h);
        upk2(qa4.y, l, h); ull qb = pk2(-2.f*l, -2.f*h);
        upk2(qb4.x, l, h); ull qc = pk2(-2.f*l, -2.f*h);
        upk2(qb4.y, l, h); ull qd = pk2(-2.f*l, -2.f*h);
        upk2(qc4.x, l, h); ull qe = pk2(-2.f*l, -2.f*h);
        upk2(qc4.y, l, h); ull qf = pk2(-2.f*l, -2.f*h);
        upk2(qd4.x, l, h); ull qg = pk2(-2.f*l, -2.f*h);
        upk2(qd4.y, l, h); ull qh = pk2(-2.f*l, -2.f*h);
#pragma unroll 1
        for (int c = 0; c < WARM / 32; c++) {
            int j = jbeg + 32 * c + lane;          // range >= WARM always
            const ulonglong2* p = reinterpret_cast<const ulonglong2*>(emb + (size_t)j * E_DIM);
            ulonglong2 x = p[0], y = p[1], z = p[2], u = p[3];
            ull nA = fma2(x.x, x.x, 0ULL), nB = fma2(x.y, x.y, 0ULL);
            nA = fma2(y.x, y.x, nA);  nB = fma2(y.y, y.y, nB);
            nA = fma2(z.x, z.x, nA);  nB = fma2(z.y, z.y, nB);
            nA = fma2(u.x, u.x, nA);  nB = fma2(u.y, u.y, nB);
            ull a = fma2(qa, x.x, nA);
            a = fma2(qb, x.y, a);  a = fma2(qc, y.x, a);
            a = fma2(qd, y.y, a);  a = fma2(qe, z.x, a);
            a = fma2(qf, z.y, a);  a = fma2(qg, u.x, a);
            a = fma2(qh, u.y, a);
            float lo, hi, lo2, hi2;
            upk2(a, lo, hi); upk2(nB, lo2, hi2);
            float s = lo + hi + lo2 + hi2;
            uint m = __ballot_sync(FULLM, s < wth);
            while (m) {
                int src = __ffs(m) - 1; m &= m - 1;
                float bv = __shfl_sync(FULLM, s, src);
                int   bj = jbeg + 32 * c + src;
                if (bv < wth) {
                    float pv = __shfl_up_sync(FULLM, wkv, 1);
                    int   pj = __shfl_up_sync(FULLM, wki, 1);
                    if (lane < KP1 && bv < wkv) {
                        if (lane == 0 || bv >= pv) { wkv = bv; wki = bj; }
                        else                        { wkv = pv; wki = pj; }
                    }
                    wth = __shfl_sync(FULLM, wkv, KP1 - 1);
                }
            }
        }
        if (lane == 0) th_sm[w] = wth;
    }

    // ---- q2: all 8 rows, own half dims, packed -2*q (64 regs) ----
    ull q2[G_ROWS][4];
#pragma unroll
    for (int r = 0; r < G_ROWS; r++) {
        int si = idxp[rowbase + r];
        const float4* qp = reinterpret_cast<const float4*>(
            emb + (size_t)si * E_DIM + 8 * half);
        float4 v0 = qp[0], v1 = qp[1];
        q2[r][0] = pk2(-2.f * v0.x, -2.f * v0.y);
        q2[r][1] = pk2(-2.f * v0.z, -2.f * v0.w);
        q2[r][2] = pk2(-2.f * v1.x, -2.f * v1.y);
        q2[r][3] = pk2(-2.f * v1.z, -2.f * v1.w);
    }
    __syncthreads();                    // th_sm / na_sm visible

    // ---- 8 warp-distributed top-21 lists; seed list w from warm-up ----
    float kv[G_ROWS];
    int   ki[G_ROWS];
#pragma unroll
    for (int r = 0; r < G_ROWS; r++) {
        kv[r] = (r == w) ? wkv : finf();
        ki[r] = (r == w) ? wki : -1;
    }

    const int base = jbeg + WARM;
    const int nit  = (jend - base + 127) >> 7;

    const uint th_addr = (uint)__cvta_generic_to_shared(&th_sm[0]);

    // preload iter 0
    ull e0, e1, e2, e3;
    {
        int j = min(base + 16 * w + k, jend - 1);
        const ulonglong2* p = reinterpret_cast<const ulonglong2*>(
            emb + (size_t)j * E_DIM + 8 * half);
        e0 = p[0].x; e1 = p[0].y; e2 = p[1].x; e3 = p[1].y;
    }

    for (int it = 0; it < nit; it++) {
        const int jb = base + (it << 7) + 16 * w;
        // prefetch next iter (clamped; validity handled by gate)
        ull f0, f1, f2, f3;
        {
            int j = min(jb + 128 + k, jend - 1);
            const ulonglong2* p = reinterpret_cast<const ulonglong2*>(
                emb + (size_t)j * E_DIM + 8 * half);
            f0 = p[0].x; f1 = p[0].y; f2 = p[1].x; f3 = p[1].y;
        }
        // partial s over own 8 dims
        ull nrm = fma2(e0, e0, fma2(e1, e1, fma2(e2, e2, fma2(e3, e3, 0ULL))));
        float s[G_ROWS];
#pragma unroll
        for (int r = 0; r < G_ROWS; r++) {
            ull a = fma2(q2[r][0], e0,
                    fma2(q2[r][1], e1,
                    fma2(q2[r][2], e2,
                    fma2(q2[r][3], e3, nrm))));
            float lo, hi; upk2(a, lo, hi);
            s[r] = lo + hi;
        }
        // combine halves: one shfl per row
#pragma unroll
        for (int r = 0; r < G_ROWS; r++)
            s[r] += __shfl_xor_sync(FULLM, s[r], 1);

        // gate: volatile threshold read + min-tree any-hit
        float t0, t1, t2, t3, t4, t5, t6, t7;
        asm volatile("ld.volatile.shared.v4.f32 {%0,%1,%2,%3},[%4];"
                     : "=f"(t0), "=f"(t1), "=f"(t2), "=f"(t3) : "r"(th_addr));
        asm volatile("ld.volatile.shared.v4.f32 {%0,%1,%2,%3},[%4];"
                     : "=f"(t4), "=f"(t5), "=f"(t6), "=f"(t7) : "r"(th_addr + 16));
        const float thg[8] = {t0, t1, t2, t3, t4, t5, t6, t7};
        const int  j    = jb + k;
        const bool vld  = (j < jend);
        float hmin = s[0] - thg[0];
        hmin = fminf(hmin, s[1] - thg[1]);
        hmin = fminf(hmin, s[2] - thg[2]);
        hmin = fminf(hmin, s[3] - thg[3]);
        hmin = fminf(hmin, s[4] - thg[4]);
        hmin = fminf(hmin, s[5] - thg[5]);
        hmin = fminf(hmin, s[6] - thg[6]);
        hmin = fminf(hmin, s[7] - thg[7]);
        if (!vld) hmin = 1.f;

        if (__any_sync(FULLM, hmin < 0.f)) {        // rare slow path
#pragma unroll
            for (int r = 0; r < G_ROWS; r++) {
                uint m = __ballot_sync(FULLM, vld && s[r] < thg[r]) & 0x55555555u;
                if (m) {
                    float lth = __shfl_sync(FULLM, kv[r], KP1 - 1);
                    while (m) {
                        int src = __ffs(m) - 1; m &= m - 1;
                        float bv = __shfl_sync(FULLM, s[r], src);
                        int   bj = jb + (src >> 1);
                        if (bv < lth) {
                            float pv = __shfl_up_sync(FULLM, kv[r], 1);
                            int   pj = __shfl_up_sync(FULLM, ki[r], 1);
                            if (lane < KP1 && bv < kv[r]) {
                                if (lane == 0 || bv >= pv) { kv[r] = bv; ki[r] = bj; }
                                else                        { kv[r] = pv; ki[r] = pj; }
                            }
                            lth = __shfl_sync(FULLM, kv[r], KP1 - 1);
                        }
                    }
                    if (lane == 0) th_sm[r] = lth;   // plain store: any list's
                }                                     // 21st is a safe bound
            }
        }
        e0 = f0; e1 = f1; e2 = f2; e3 = f3;
    }

    // ================= block merge: warp w finalizes row w =================
    if (lane < KP1) {
#pragma unroll
        for (int r = 0; r < G_ROWS; r++)
            lst[w][r][lane] = (((ull)(uint)ki[r]) << 32) | __float_as_uint(kv[r]);
    }
    __syncthreads();

    float kvF = finf(), thF = finf();
    int   kiF = -1;
    auto insF = [&](float bv, int bj) {
        float pv = __shfl_up_sync(FULLM, kvF, 1);
        int   pj = __shfl_up_sync(FULLM, kiF, 1);
        if (lane < KP1 && bv < kvF) {
            if (lane == 0 || bv >= pv) { kvF = bv; kiF = bj; }
            else                        { kvF = pv; kiF = pj; }
        }
        thF = __shfl_sync(FULLM, kvF, KP1 - 1);
    };
#pragma unroll 1
    for (int ww = 0; ww < G_ROWS; ww++) {
        float bvl = finf(); int bjl = -1;
        if (lane < KP1) {
            ull ent = lst[ww][w][lane];
            bvl = __uint_as_float((uint)ent);
            bjl = (int)(ent >> 32);
        }
        uint m = __ballot_sync(FULLM, bvl < thF);
        while (m) {
            int src = __ffs(m) - 1; m &= m - 1;
            float bv = __shfl_sync(FULLM, bvl, src);
            int   bj = __shfl_sync(FULLM, bjl, src);
            if (bv < thF) insF(bv, bj);
        }
    }

    // ================= split rendezvous =================
    if (lane < KP1) {
        g_pval[set][grp][split][w][lane] = kvF;
        g_pidx[set][grp][split][w][lane] = kiF;
    }
    __threadfence();
    __syncthreads();
    if (tid == 0) smflag[0] = atomicAdd(&g_flag[set][grp], 1);
    __syncthreads();

    if (smflag[0] == SPLITS - 1) {          // last arrival merges + features
        __threadfence();
#pragma unroll 1
        for (int s2 = 0; s2 < SPLITS; s2++) {
            if (s2 == split) continue;
            for (int i = 0; i < KP1; i++) {
                float bv = g_pval[set][grp][s2][w][i];
                int   bj = g_pidx[set][grp][s2][w][i];
                if (bv < thF) insF(bv, bj);
            }
        }
        // lane 0 = "self" (s = -|a|^2, strict global min): dropped
        const int row = rowbase + w;
        const float na = na_sm[w];
        float wgt = 0.f, sel = 0.f;
        if (lane >= 1 && lane < KP1) {
            float d2  = fmaxf(kvF + na, 0.f);
            float sim = sqrtf(d2) + 0.001f;
            wgt = __expf(-sim);
            sel = rctx[(size_t)row * n + kiF];
        }
        float sw = wgt, ssw = sel * wgt, ss = sel, ss2 = sel * sel;
#pragma unroll
        for (int off = 16; off; off >>= 1) {
            sw  += __shfl_xor_sync(FULLM, sw,  off);
            ssw += __shfl_xor_sync(FULLM, ssw, off);
            ss  += __shfl_xor_sync(FULLM, ss,  off);
            ss2 += __shfl_xor_sync(FULLM, ss2, off);
        }
        if (lane == 0) {
            g_feats[row][0 + set] = sw;
            g_feats[row][2 + set] = ssw / sw;
            float var = (ss2 - ss * ss / (float)KSEL) / (float)(KSEL - 1);
            g_feats[row][4 + set] = sqrtf(fmaxf(var, 0.f));
        }
        if (tid == 0) g_flag[set][grp] = 0;
    }

    // ================= global tail: MLP =================
    __threadfence();
    __syncthreads();
    if (tid == 0) smflag[1] = atomicAdd(&g_done, 1);
    __syncthreads();
    if (smflag[1] != NBLK - 1) return;
    __threadfence();

#pragma unroll
    for (int rr = 0; rr < 2; rr++) {
        int r = tid + BTHR * rr;
        float f[8];
#pragma unroll
        for (int i = 0; i < 6; i++) f[i] = g_feats[r][i];
        f[6] = mean_in[r];
        f[7] = std_in[r];
        float m = bm[0], sd = bs[0];
#pragma unroll 4
        for (int jj = 0; jj < HID; jj++) {
            float h = b1[jj];
#pragma unroll
            for (int i = 0; i < 8; i++) h = fmaf(f[i], W1[i * HID + jj], h);
            h = fmaxf(h, 0.f);
            m  = fmaf(h, Wm[jj], m);
            sd = fmaf(h, Ws[jj], sd);
        }
        out[r]          = m;
        out[B_ROWS + r] = sd;
    }
    if (tid == 0) g_done = 0;
}

// ---------------------------------------------------------------------------
extern "C" void kernel_launch(void* const* d_in, const int* in_sizes, int n_in,
                              void* d_out, int out_size) {
    const float* emb0    = (const float*)d_in[0];
    const float* emb1    = (const float*)d_in[1];
    const float* rctx0   = (const float*)d_in[2];
    const float* rctx1   = (const float*)d_in[3];
    const int*   idx0    = (const int*)  d_in[4];
    const int*   idx1    = (const int*)  d_in[5];
    const float* mean_in = (const float*)d_in[6];
    const float* std_in  = (const float*)d_in[7];
    const float* W1      = (const float*)d_in[8];
    const float* b1      = (const float*)d_in[9];
    const float* Wm      = (const float*)d_in[10];
    const float* bm      = (const float*)d_in[11];
    const float* Ws      = (const float*)d_in[12];
    const float* bs      = (const float*)d_in[13];

    int n = in_sizes[0] / E_DIM;    // 50000

    dim3 grid(NGRP, 2, SPLITS);
    knn_kernel<<<grid, BTHR>>>(emb0, emb1, rctx0, rctx1, idx0, idx1,
                               mean_in, std_in, W1, b1, Wm, bm, Ws, bs,
                               (float*)d_out, n);
}

// round 14
// speedup vs baseline: 1.2192x; 1.0133x over previous
#include <cuda_runtime.h>
#include <stdint.h>

#define N_PTS   50000
#define B_ROWS  512
#define E_DIM   16
#define KSEL    20
#define TILE    64           // candidates per tile (1 per sub-group thread)
#define BTHR    256          // 4 sub-groups x 64 threads
#define G_ROWS  8
#define SPLITS  4
#define NGRP    (B_ROWS / G_ROWS)        // 64
#define NBLK    (NGRP * 2 * SPLITS)      // 512
#define HID     64
#define FULLM   0xffffffffu

typedef unsigned long long ull;
typedef unsigned int uint;

__device__ float g_feats[B_ROWS][8];
__device__ float g_pval[2][NGRP][SPLITS][G_ROWS][KSEL];
__device__ int   g_pidx[2][NGRP][SPLITS][G_ROWS][KSEL];
__device__ int   g_flag[2][NGRP];
__device__ int   g_done = 0;

static __device__ __forceinline__ float finf() { return __int_as_float(0x7f800000); }

static __device__ __forceinline__ ull pk2(float lo, float hi) {
    ull r; asm("mov.b64 %0,{%1,%2};" : "=l"(r) : "f"(lo), "f"(hi)); return r;
}
static __device__ __forceinline__ void upk2(ull v, float& lo, float& hi) {
    asm("mov.b64 {%0,%1},%2;" : "=f"(lo), "=f"(hi) : "l"(v));
}
static __device__ __forceinline__ ull fma2(ull a, ull b, ull c) {
    ull d; asm("fma.rn.f32x2 %0,%1,%2,%3;" : "=l"(d) : "l"(a), "l"(b), "l"(c)); return d;
}
static __device__ __forceinline__ ull add2(ull a, ull b) {
    ull d; asm("add.rn.f32x2 %0,%1,%2;" : "=l"(d) : "l"(a), "l"(b)); return d;
}

// ---------------------------------------------------------------------------
// Quarter-split (dims x rows) KNN at occupancy 3.
// grid = (64 groups, 2 sets, 4 splits) = 512 blocks x 256 threads.
// Sub-group (d, rh) of 64 threads owns dims [8d,8d+8) of rows [4rh,4rh+4):
//   q2 = 4 rows x 8 dims packed = 32 regs -> ~82 regs/thread -> 3 blocks/SM.
// Phase A: thread computes quarter-partials (half-norm folded) -> sbuf[d][row].
// Phase B: warp w sums the two dim-halves of row w (2 LDS.64), full scan,
//   warp-distributed sorted top-20 (explicit self-exclusion).
// One barrier per 64-candidate tile; prefetch(t+1) issued before phaseB(t-1).
// ---------------------------------------------------------------------------
__global__ __launch_bounds__(BTHR, 3)
void knn_kernel(const float* __restrict__ emb0, const float* __restrict__ emb1,
                const float* __restrict__ rctx0, const float* __restrict__ rctx1,
                const int* __restrict__ idx0, const int* __restrict__ idx1,
                const float* __restrict__ mean_in, const float* __restrict__ std_in,
                const float* __restrict__ W1, const float* __restrict__ b1,
                const float* __restrict__ Wm, const float* __restrict__ bm,
                const float* __restrict__ Ws, const float* __restrict__ bs,
                float* __restrict__ out, int n) {
    const int grp   = blockIdx.x;
    const int set   = blockIdx.y;
    const int split = blockIdx.z;
    const float* __restrict__ emb  = set ? emb1 : emb0;
    const float* __restrict__ rctx = set ? rctx1 : rctx0;
    const int*   __restrict__ idxp = set ? idx1 : idx0;

    const int rowbase = grp * G_ROWS;
    const int tid  = threadIdx.x;
    const int lane = tid & 31;
    const int w    = tid >> 5;          // warp 0..7 == row owner in phase B
    const int sg   = tid >> 6;          // sub-group 0..3
    const int d    = sg & 1;            // dim half
    const int rh   = sg >> 1;           // row half
    const int lt   = tid & 63;          // candidate slot within tile

    __shared__ float sbuf[2][2][G_ROWS][TILE];  // [buf][dimhalf][row][cand] 8KB
    __shared__ float na_sm[G_ROWS];
    __shared__ int   self_sm[G_ROWS];
    __shared__ int   smflag[2];

    // ---- staging: warp w computes |a|^2 + self idx for row w ----
    {
        int si = 0;
        if (lane == 0) si = idxp[rowbase + w];
        si = __shfl_sync(FULLM, si, 0);
        if (lane == 0) self_sm[w] = si;
        float nx = 0.f;
        if (lane < 8) {
            float2 v = reinterpret_cast<const float2*>(emb + (size_t)si * E_DIM)[lane];
            nx = v.x * v.x + v.y * v.y;
        }
        nx += __shfl_xor_sync(FULLM, nx, 4);
        nx += __shfl_xor_sync(FULLM, nx, 2);
        nx += __shfl_xor_sync(FULLM, nx, 1);
        if (lane == 0) na_sm[w] = nx;
    }

    // ---- q2: own 4 rows x own 8 dims, packed -2*q (32 regs) ----
    ull q2[4][4];
#pragma unroll
    for (int r = 0; r < 4; r++) {
        int si = idxp[rowbase + 4 * rh + r];
        const float4* qp = reinterpret_cast<const float4*>(
            emb + (size_t)si * E_DIM + 8 * d);
        float4 v0 = qp[0], v1 = qp[1];
        q2[r][0] = pk2(-2.f * v0.x, -2.f * v0.y);
        q2[r][1] = pk2(-2.f * v0.z, -2.f * v0.w);
        q2[r][2] = pk2(-2.f * v1.x, -2.f * v1.y);
        q2[r][3] = pk2(-2.f * v1.z, -2.f * v1.w);
    }
    __syncthreads();
    const int selfi = self_sm[w];

    const int halfn  = (n + SPLITS - 1) / SPLITS;   // 12500
    const int jbeg   = split * halfn;
    const int jend   = min(n, jbeg + halfn);
    const int ntiles = (jend - jbeg + TILE - 1) / TILE;

    // ---- top-k state (lanes 0..19 ascending) ----
    float kval   = finf();
    int   kidx   = -1;
    float thresh = finf();

    auto insert = [&](float bv, int bj) {
        float pv = __shfl_up_sync(FULLM, kval, 1);
        int   pj = __shfl_up_sync(FULLM, kidx, 1);
        if (lane < KSEL && bv < kval) {
            if (lane == 0 || bv >= pv) { kval = bv; kidx = bj; }
            else                        { kval = pv; kidx = pj; }
        }
        thresh = __shfl_sync(FULLM, kval, KSEL - 1);
    };
    auto scatter = [&](float s, int j, bool ok) {
        uint m = __ballot_sync(FULLM, ok && s < thresh);
        while (m) {
            int src = __ffs(m) - 1; m &= m - 1;
            float bv = __shfl_sync(FULLM, s, src);
            int   bj = __shfl_sync(FULLM, j, src);
            if (bv < thresh) insert(bv, bj);
        }
    };

    // ---- phase B: warp w sums halves of row w, scans 64 cands ----
    auto phaseB = [&](int t) {
        const int buf  = t & 1;
        const int base = jbeg + t * TILE;
        float2 a0 = *reinterpret_cast<const float2*>(&sbuf[buf][0][w][2 * lane]);
        float2 a1 = *reinterpret_cast<const float2*>(&sbuf[buf][1][w][2 * lane]);
        float s0 = a0.x + a1.x;
        float s1 = a0.y + a1.y;
        int   j0 = base + 2 * lane;
        int   j1 = j0 + 1;
        scatter(s0, j0, (j0 != selfi) && (j0 < jend));
        scatter(s1, j1, (j1 != selfi) && (j1 < jend));
    };

    // ---- main loop: prefetch(t+1) -> phaseB(t-1) -> phaseA(t) -> bar ----
    ull eC[4], eN[4];
    {   // preload tile 0 (clamped; masked in phase B)
        int j = min(jbeg + lt, jend - 1);
        const ulonglong2* p = reinterpret_cast<const ulonglong2*>(
            emb + (size_t)j * E_DIM + 8 * d);
        eC[0] = p[0].x; eC[1] = p[0].y; eC[2] = p[1].x; eC[3] = p[1].y;
    }

    for (int t = 0; t < ntiles; t++) {
        // prefetch next tile
        if (t + 1 < ntiles) {
            int j = min(jbeg + (t + 1) * TILE + lt, jend - 1);
            const ulonglong2* p = reinterpret_cast<const ulonglong2*>(
                emb + (size_t)j * E_DIM + 8 * d);
            eN[0] = p[0].x; eN[1] = p[0].y; eN[2] = p[1].x; eN[3] = p[1].y;
        }
        // phase B of previous tile hides the LDG latency
        if (t > 0) phaseB(t - 1);

        // phase A: half-norm + 4-row quarter dot products
        const int buf = t & 1;
        ull nA = fma2(eC[0], eC[0], 0ULL), nB = fma2(eC[1], eC[1], 0ULL);
        nA = fma2(eC[2], eC[2], nA);  nB = fma2(eC[3], eC[3], nB);
        ull nrm = add2(nA, nB);
        ull acc[4];
#pragma unroll
        for (int r = 0; r < 4; r++) acc[r] = nrm;
#pragma unroll
        for (int k = 0; k < 4; k++) {
            ull ek = eC[k];
            acc[0] = fma2(q2[0][k], ek, acc[0]);
            acc[1] = fma2(q2[1][k], ek, acc[1]);
            acc[2] = fma2(q2[2][k], ek, acc[2]);
            acc[3] = fma2(q2[3][k], ek, acc[3]);
        }
#pragma unroll
        for (int r = 0; r < 4; r++) {
            float lo, hi; upk2(acc[r], lo, hi);
            sbuf[buf][d][4 * rh + r][lt] = lo + hi;
        }
        __syncthreads();

#pragma unroll
        for (int k = 0; k < 4; k++) eC[k] = eN[k];
    }
    phaseB(ntiles - 1);

    // ================= split rendezvous (4 partials) =================
    if (lane < KSEL) {
        g_pval[set][grp][split][w][lane] = kval;
        g_pidx[set][grp][split][w][lane] = kidx;
    }
    __threadfence();
    __syncthreads();
    if (tid == 0) smflag[0] = atomicAdd(&g_flag[set][grp], 1);
    __syncthreads();

    if (smflag[0] == SPLITS - 1) {          // last arrival merges + features
        __threadfence();
#pragma unroll 1
        for (int s2 = 0; s2 < SPLITS; s2++) {
            if (s2 == split) continue;
            for (int i = 0; i < KSEL; i++) {
                float bv = g_pval[set][grp][s2][w][i];
                int   bj = g_pidx[set][grp][s2][w][i];
                if (bv < thresh) insert(bv, bj);
            }
        }
        const int row = rowbase + w;
        const float na = na_sm[w];
        float wgt = 0.f, sel = 0.f;
        if (lane < KSEL) {
            float d2  = fmaxf(kval + na, 0.f);
            float sim = sqrtf(d2) + 0.001f;
            wgt = __expf(-sim);
            sel = rctx[(size_t)row * n + kidx];
        }
        float sw = wgt, ssw = sel * wgt, ss = sel, ss2 = sel * sel;
#pragma unroll
        for (int off = 16; off; off >>= 1) {
            sw  += __shfl_xor_sync(FULLM, sw,  off);
            ssw += __shfl_xor_sync(FULLM, ssw, off);
            ss  += __shfl_xor_sync(FULLM, ss,  off);
            ss2 += __shfl_xor_sync(FULLM, ss2, off);
        }
        if (lane == 0) {
            g_feats[row][0 + set] = sw;
            g_feats[row][2 + set] = ssw / sw;
            float var = (ss2 - ss * ss / (float)KSEL) / (float)(KSEL - 1);
            g_feats[row][4 + set] = sqrtf(fmaxf(var, 0.f));
        }
        if (tid == 0) g_flag[set][grp] = 0;
    }

    // ================= global tail: MLP =================
    __threadfence();
    __syncthreads();
    if (tid == 0) smflag[1] = atomicAdd(&g_done, 1);
    __syncthreads();
    if (smflag[1] != NBLK - 1) return;
    __threadfence();

#pragma unroll
    for (int rr = 0; rr < 2; rr++) {
        int r = tid + BTHR * rr;
        float f[8];
#pragma unroll
        for (int i = 0; i < 6; i++) f[i] = g_feats[r][i];
        f[6] = mean_in[r];
        f[7] = std_in[r];
        float m = bm[0], sd = bs[0];
#pragma unroll 4
        for (int jj = 0; jj < HID; jj++) {
            float h = b1[jj];
#pragma unroll
            for (int i = 0; i < 8; i++) h = fmaf(f[i], W1[i * HID + jj], h);
            h = fmaxf(h, 0.f);
            m  = fmaf(h, Wm[jj], m);
            sd = fmaf(h, Ws[jj], sd);
        }
        out[r]          = m;
        out[B_ROWS + r] = sd;
    }
    if (tid == 0) g_done = 0;
}

// ---------------------------------------------------------------------------
extern "C" void kernel_launch(void* const* d_in, const int* in_sizes, int n_in,
                              void* d_out, int out_size) {
    const float* emb0    = (const float*)d_in[0];
    const float* emb1    = (const float*)d_in[1];
    const float* rctx0   = (const float*)d_in[2];
    const float* rctx1   = (const float*)d_in[3];
    const int*   idx0    = (const int*)  d_in[4];
    const int*   idx1    = (const int*)  d_in[5];
    const float* mean_in = (const float*)d_in[6];
    const float* std_in  = (const float*)d_in[7];
    const float* W1      = (const float*)d_in[8];
    const float* b1      = (const float*)d_in[9];
    const float* Wm      = (const float*)d_in[10];
    const float* bm      = (const float*)d_in[11];
    const float* Ws      = (const float*)d_in[12];
    const float* bs      = (const float*)d_in[13];

    int n = in_sizes[0] / E_DIM;    // 50000

    dim3 grid(NGRP, 2, SPLITS);
    knn_kernel<<<grid, BTHR>>>(emb0, emb1, rctx0, rctx1, idx0, idx1,
                               mean_in, std_in, W1, b1, Wm, bm, Ws, bs,
                               (float*)d_out, n);
}

// round 15
// speedup vs baseline: 1.2600x; 1.0335x over previous
#include <cuda_runtime.h>
#include <stdint.h>

#define N_PTS   50000
#define B_ROWS  512
#define E_DIM   16
#define KSEL    20
#define TILE    128          // candidates per tile (1 per group-thread)
#define BTHR    256          // 2 dim-groups x 128 threads
#define G_ROWS  8
#define SPLITS  7            // 896 blocks -> ~5.9/SM at occ 2: wave-balanced
#define NGRP    (B_ROWS / G_ROWS)      // 64
#define NBLK    (NGRP * 2 * SPLITS)    // 896
#define HID     64
#define FULLM   0xffffffffu
#define BIGV    1.0e37f

typedef unsigned long long ull;

__device__ float g_feats[B_ROWS][8];
__device__ float g_pval[2][NGRP][SPLITS][G_ROWS][KSEL];
__device__ int   g_pidx[2][NGRP][SPLITS][G_ROWS][KSEL];
__device__ int   g_flag[2][NGRP];
__device__ int   g_done = 0;

static __device__ __forceinline__ float finf() { return __int_as_float(0x7f800000); }

static __device__ __forceinline__ ull pk2(float lo, float hi) {
    ull r; asm("mov.b64 %0,{%1,%2};" : "=l"(r) : "f"(lo), "f"(hi)); return r;
}
static __device__ __forceinline__ void upk2(ull v, float& lo, float& hi) {
    asm("mov.b64 {%0,%1},%2;" : "=f"(lo), "=f"(hi) : "l"(v));
}
static __device__ __forceinline__ ull fma2(ull a, ull b, ull c) {
    ull d; asm("fma.rn.f32x2 %0,%1,%2,%3;" : "=l"(d) : "l"(a), "l"(b), "l"(c)); return d;
}
static __device__ __forceinline__ ull add2(ull a, ull b) {
    ull d; asm("add.rn.f32x2 %0,%1,%2;" : "=l"(d) : "l"(a), "l"(b)); return d;
}

// ---------------------------------------------------------------------------
// DIMENSION-SPLIT kernel (R9 structure, wave-balanced grid).
// grid = (64 groups, 2 sets, 7 splits), block = 256.
// Thread-group g (128 threads) owns dims [8g, 8g+8) of every candidate:
//   - q for ALL 8 rows but only 8 dims -> 64 regs/thread (occupancy-safe)
//   - candidate bytes are read ONCE per block (groups read complementary halves)
//   - each group writes partial s (half-norm + half-dot) to sbuf[g][row][cand]
// Phase B: warp w = row w: sum the two halves, hitmask + redux, sorted
// warp-distributed top-20 insert. Threshold lives in-warp only.
// ---------------------------------------------------------------------------
__global__ __launch_bounds__(BTHR, 2)
void knn_kernel(const float* __restrict__ emb0, const float* __restrict__ emb1,
                const float* __restrict__ rctx0, const float* __restrict__ rctx1,
                const int* __restrict__ idx0, const int* __restrict__ idx1,
                const float* __restrict__ mean_in, const float* __restrict__ std_in,
                const float* __restrict__ W1, const float* __restrict__ b1,
                const float* __restrict__ Wm, const float* __restrict__ bm,
                const float* __restrict__ Ws, const float* __restrict__ bs,
                float* __restrict__ out, int n) {
    const int grp   = blockIdx.x;
    const int set   = blockIdx.y;
    const int split = blockIdx.z;
    const float* __restrict__ emb  = set ? emb1 : emb0;
    const float* __restrict__ rctx = set ? rctx1 : rctx0;
    const int*   __restrict__ idxp = set ? idx1 : idx0;

    const int rowbase = grp * G_ROWS;
    const int tid  = threadIdx.x;
    const int lane = tid & 31;
    const int w    = tid >> 5;          // warp 0..7 == row owner in phase B
    const int g    = tid >> 7;          // dim-group 0/1 -> dims 8g..8g+7
    const int lt   = tid & 127;         // candidate slot within tile

    __shared__ float sbuf[2][2][G_ROWS][TILE];  // [buf][dimgrp][row][cand] 32KB
    __shared__ float na_sm[G_ROWS];
    __shared__ int   self_sm[G_ROWS];
    __shared__ int   smflag[2];

    // ---- stage self idx + |a|^2 (warp r handles row r) ----
    if (w < G_ROWS) {
        int si = 0;
        if (lane == 0) si = idxp[rowbase + w];
        si = __shfl_sync(FULLM, si, 0);
        if (lane == 0) self_sm[w] = si;
        float nx = 0.f;
        if (lane < 8) {
            float2 v = reinterpret_cast<const float2*>(emb + (size_t)si * E_DIM)[lane];
            nx = v.x * v.x + v.y * v.y;
        }
        nx += __shfl_xor_sync(FULLM, nx, 4);
        nx += __shfl_xor_sync(FULLM, nx, 2);
        nx += __shfl_xor_sync(FULLM, nx, 1);
        if (lane == 0) na_sm[w] = nx;
    }

    // ---- q for all 8 rows, THIS group's 8 dims, packed -2*q: 32 ull ----
    ull q2[G_ROWS][4];
#pragma unroll
    for (int r = 0; r < G_ROWS; r++) {
        int si = idxp[rowbase + r];
        const float4* qp = reinterpret_cast<const float4*>(
            emb + (size_t)si * E_DIM + 8 * g);
        float4 v0 = qp[0], v1 = qp[1];
        q2[r][0] = pk2(-2.f * v0.x, -2.f * v0.y);
        q2[r][1] = pk2(-2.f * v0.z, -2.f * v0.w);
        q2[r][2] = pk2(-2.f * v1.x, -2.f * v1.y);
        q2[r][3] = pk2(-2.f * v1.z, -2.f * v1.w);
    }
    __syncthreads();
    const int selfi = self_sm[w];

    const int halfn  = (n + SPLITS - 1) / SPLITS;   // 7143
    const int jbeg   = split * halfn;
    const int jend   = min(n, jbeg + halfn);
    const int ntiles = (jend - jbeg + TILE - 1) / TILE;

    // ---- top-k state (lanes 0..19 ascending) ----
    float kval   = finf();
    int   kidx   = -1;
    float thresh = finf();

    auto insert = [&](float bv, int bj) {
        float pv = __shfl_up_sync(FULLM, kval, 1);
        int   pj = __shfl_up_sync(FULLM, kidx, 1);
        if (lane < KSEL && bv < kval) {
            if (lane == 0 || bv >= pv) { kval = bv; kidx = bj; }
            else                        { kval = pv; kidx = pj; }
        }
        thresh = __shfl_sync(FULLM, kval, KSEL - 1);
    };

    // ---- phase B: warp w sums halves of row w, scans 128 cands ----
    auto phaseB = [&](int t) {
        const int buf  = t & 1;
        const int base = jbeg + t * TILE;
        float4 a = reinterpret_cast<const float4*>(&sbuf[buf][0][w][0])[lane];
        float4 b = reinterpret_cast<const float4*>(&sbuf[buf][1][w][0])[lane];
        float v[4] = {a.x + b.x, a.y + b.y, a.z + b.z, a.w + b.w};
        unsigned hm = 0;
#pragma unroll
        for (int i = 0; i < 4; i++) {
            int j = base + 4 * lane + i;
            if (v[i] < thresh && j != selfi) hm |= (1u << i);
        }
        unsigned red = __reduce_or_sync(FULLM, hm);
        while (red) {
            int i = __ffs(red) - 1; red &= red - 1;
            unsigned m = __ballot_sync(FULLM, (hm >> i) & 1u);
            float vi = v[i];
            int   ji = base + 4 * lane + i;
            while (m) {
                int src = __ffs(m) - 1; m &= m - 1;
                float bv = __shfl_sync(FULLM, vi, src);
                int   bj = __shfl_sync(FULLM, ji, src);
                if (bv < thresh) insert(bv, bj);
            }
        }
    };

    // ---- main loop ----
    ull e[4];                            // this group's 32B of the candidate
    bool vld;
    {
        int j = jbeg + lt;
        vld = (j < jend);
        if (vld) {
            const ulonglong2* p = reinterpret_cast<const ulonglong2*>(
                emb + (size_t)j * E_DIM + 8 * g);
            ulonglong2 x = p[0], y = p[1];
            e[0] = x.x; e[1] = x.y; e[2] = y.x; e[3] = y.y;
        }
    }

    for (int t = 0; t < ntiles; t++) {
        const int buf = t & 1;
        // partial s = half-norm + half-dot for all 8 rows
        ull nA = fma2(e[0], e[0], 0), nB = fma2(e[1], e[1], 0);
        nA = fma2(e[2], e[2], nA);     nB = fma2(e[3], e[3], nB);
        ull nrm = add2(nA, nB);
        ull acc[G_ROWS];
#pragma unroll
        for (int r = 0; r < G_ROWS; r++) acc[r] = nrm;
#pragma unroll
        for (int k = 0; k < 4; k++) {
            ull ek = e[k];
#pragma unroll
            for (int r = 0; r < G_ROWS; r++)
                acc[r] = fma2(q2[r][k], ek, acc[r]);
        }
#pragma unroll
        for (int r = 0; r < G_ROWS; r++) {
            float lo, hi; upk2(acc[r], lo, hi);
            sbuf[buf][g][r][lt] = vld ? (lo + hi) : BIGV;
        }
        // prefetch next tile (covered by barrier + phaseB)
        if (t + 1 < ntiles) {
            int j = jbeg + (t + 1) * TILE + lt;
            vld = (j < jend);
            if (vld) {
                const ulonglong2* p = reinterpret_cast<const ulonglong2*>(
                    emb + (size_t)j * E_DIM + 8 * g);
                ulonglong2 x = p[0], y = p[1];
                e[0] = x.x; e[1] = x.y; e[2] = y.x; e[3] = y.y;
            }
        }
        __syncthreads();
        phaseB(t);
    }

    // ---- split rendezvous (7 partials) ----
    if (lane < KSEL) {
        g_pval[set][grp][split][w][lane] = kval;
        g_pidx[set][grp][split][w][lane] = kidx;
    }
    __threadfence();
    __syncthreads();
    if (tid == 0) smflag[0] = atomicAdd(&g_flag[set][grp], 1);
    __syncthreads();

    if (smflag[0] == SPLITS - 1) {      // last arrival merges + features
        __threadfence();
#pragma unroll 1
        for (int s2 = 0; s2 < SPLITS; s2++) {
            if (s2 == split) continue;
            for (int i = 0; i < KSEL; i++) {
                float bv = g_pval[set][grp][s2][w][i];
                int   bj = g_pidx[set][grp][s2][w][i];
                if (bv < thresh) insert(bv, bj);
            }
        }
        const int row = rowbase + w;
        const float na = na_sm[w];
        float wgt = 0.f, sel = 0.f;
        if (lane < KSEL) {
            float d2  = fmaxf(kval + na, 0.f);
            float sim = sqrtf(d2) + 0.001f;
            wgt = __expf(-sim);
            sel = rctx[(size_t)row * n + kidx];
        }
        float sw = wgt, ssw = sel * wgt, ss = sel, ss2 = sel * sel;
#pragma unroll
        for (int off = 16; off; off >>= 1) {
            sw  += __shfl_xor_sync(FULLM, sw,  off);
            ssw += __shfl_xor_sync(FULLM, ssw, off);
            ss  += __shfl_xor_sync(FULLM, ss,  off);
            ss2 += __shfl_xor_sync(FULLM, ss2, off);
        }
        if (lane == 0) {
            g_feats[row][0 + set] = sw;
            g_feats[row][2 + set] = ssw / sw;
            float var = (ss2 - ss * ss / (float)KSEL) / (float)(KSEL - 1);
            g_feats[row][4 + set] = sqrtf(fmaxf(var, 0.f));
        }
        if (tid == 0) g_flag[set][grp] = 0;
    }

    // ---- global tail: MLP ----
    __threadfence();
    __syncthreads();
    if (tid == 0) smflag[1] = atomicAdd(&g_done, 1);
    __syncthreads();
    if (smflag[1] != NBLK - 1) return;
    __threadfence();

#pragma unroll
    for (int rr = 0; rr < 2; rr++) {
        int r = tid + BTHR * rr;
        float f[8];
#pragma unroll
        for (int i = 0; i < 6; i++) f[i] = g_feats[r][i];
        f[6] = mean_in[r];
        f[7] = std_in[r];
        float m = bm[0], sd = bs[0];
#pragma unroll 4
        for (int jj = 0; jj < HID; jj++) {
            float h = b1[jj];
#pragma unroll
            for (int i = 0; i < 8; i++) h = fmaf(f[i], W1[i * HID + jj], h);
            h = fmaxf(h, 0.f);
            m  = fmaf(h, Wm[jj], m);
            sd = fmaf(h, Ws[jj], sd);
        }
        out[r]          = m;
        out[B_ROWS + r] = sd;
    }
    if (tid == 0) g_done = 0;
}

// ---------------------------------------------------------------------------
extern "C" void kernel_launch(void* const* d_in, const int* in_sizes, int n_in,
                              void* d_out, int out_size) {
    const float* emb0    = (const float*)d_in[0];
    const float* emb1    = (const float*)d_in[1];
    const float* rctx0   = (const float*)d_in[2];
    const float* rctx1   = (const float*)d_in[3];
    const int*   idx0    = (const int*)  d_in[4];
    const int*   idx1    = (const int*)  d_in[5];
    const float* mean_in = (const float*)d_in[6];
    const float* std_in  = (const float*)d_in[7];
    const float* W1      = (const float*)d_in[8];
    const float* b1      = (const float*)d_in[9];
    const float* Wm      = (const float*)d_in[10];
    const float* bm      = (const float*)d_in[11];
    const float* Ws      = (const float*)d_in[12];
    const float* bs      = (const float*)d_in[13];

    int n = in_sizes[0] / E_DIM;    // 50000

    dim3 grid(NGRP, 2, SPLITS);
    knn_kernel<<<grid, BTHR>>>(emb0, emb1, rctx0, rctx1, idx0, idx1,
                               mean_in, std_in, W1, b1, Wm, bm, Ws, bs,
                               (float*)d_out, n);
}

// round 16
// speedup vs baseline: 1.7368x; 1.3785x over previous
#include <cuda_runtime.h>
#include <stdint.h>

#define N_PTS   50000
#define B_ROWS  512
#define E_DIM   16
#define KSEL    20
#define TILE    128          // candidates per tile (2 threads per candidate)
#define BTHR    256
#define G_ROWS  8
#define SPLITS  2
#define NGRP    (B_ROWS / G_ROWS)      // 64
#define NBLK    (NGRP * 2 * SPLITS)    // 256
#define HID     64
#define FULLM   0xffffffffu
#define BIGV    1.0e37f
#define RSTRIDE 132                      // floats per sbuf row (16B aligned)
#define PLANE   (G_ROWS * RSTRIDE + 16)  // 1072 floats: %32==16 -> bank-disjoint planes

typedef unsigned long long ull;

__device__ float g_feats[B_ROWS][8];
__device__ float g_pval[2][NGRP][SPLITS][G_ROWS][KSEL];
__device__ int   g_pidx[2][NGRP][SPLITS][G_ROWS][KSEL];
__device__ int   g_flag[2][NGRP];
__device__ int   g_done = 0;

static __device__ __forceinline__ float finf() { return __int_as_float(0x7f800000); }

static __device__ __forceinline__ ull pk2(float lo, float hi) {
    ull r; asm("mov.b64 %0,{%1,%2};" : "=l"(r) : "f"(lo), "f"(hi)); return r;
}
static __device__ __forceinline__ void upk2(ull v, float& lo, float& hi) {
    asm("mov.b64 {%0,%1},%2;" : "=f"(lo), "=f"(hi) : "l"(v));
}
static __device__ __forceinline__ ull fma2(ull a, ull b, ull c) {
    ull d; asm("fma.rn.f32x2 %0,%1,%2,%3;" : "=l"(d) : "l"(a), "l"(b), "l"(c)); return d;
}
static __device__ __forceinline__ ull add2(ull a, ull b) {
    ull d; asm("add.rn.f32x2 %0,%1,%2;" : "=l"(d) : "l"(a), "l"(b)); return d;
}

// ---------------------------------------------------------------------------
// DIMENSION-SPLIT kernel with LANE-CONTIGUOUS candidate loads.
// grid = (64 groups, 2 sets, 2 splits) = 256 blocks x 256 threads, occ 2.
// Thread tid owns candidate (tid>>1), dim-half (tid&1):
//   global byte address = tilebase*64 + tid*32  -> fully contiguous LDGs
//   (halves the L1 wavefront cost vs the stride-64 record layout).
// q for all 8 rows x own half = 64 regs. Phase A writes partial s to
// sbuf[half][row][cand] (plane stride padded -> conflict-free STS/LDS).
// Phase B: warp w sums the two halves of row w, hitmask + redux, sorted
// warp-distributed top-20 insert. Threshold lives in-warp only.
// ---------------------------------------------------------------------------
__global__ __launch_bounds__(BTHR, 2)
void knn_kernel(const float* __restrict__ emb0, const float* __restrict__ emb1,
                const float* __restrict__ rctx0, const float* __restrict__ rctx1,
                const int* __restrict__ idx0, const int* __restrict__ idx1,
                const float* __restrict__ mean_in, const float* __restrict__ std_in,
                const float* __restrict__ W1, const float* __restrict__ b1,
                const float* __restrict__ Wm, const float* __restrict__ bm,
                const float* __restrict__ Ws, const float* __restrict__ bs,
                float* __restrict__ out, int n) {
    const int grp   = blockIdx.x;
    const int set   = blockIdx.y;
    const int split = blockIdx.z;
    const float* __restrict__ emb  = set ? emb1 : emb0;
    const float* __restrict__ rctx = set ? rctx1 : rctx0;
    const int*   __restrict__ idxp = set ? idx1 : idx0;

    const int rowbase = grp * G_ROWS;
    const int tid  = threadIdx.x;
    const int lane = tid & 31;
    const int w    = tid >> 5;          // warp 0..7 == row owner in phase B
    const int hf   = tid & 1;           // dim half owned by this thread
    const int cand = tid >> 1;          // candidate slot within tile (0..127)

    __shared__ float sbuf[2][2][PLANE]; // [buf][half][row*RSTRIDE + cand]
    __shared__ float na_sm[G_ROWS];
    __shared__ int   self_sm[G_ROWS];
    __shared__ int   smflag[2];

    // ---- stage self idx + |a|^2 (warp r handles row r) ----
    {
        int si = 0;
        if (lane == 0) si = idxp[rowbase + w];
        si = __shfl_sync(FULLM, si, 0);
        if (lane == 0) self_sm[w] = si;
        float nx = 0.f;
        if (lane < 8) {
            float2 v = reinterpret_cast<const float2*>(emb + (size_t)si * E_DIM)[lane];
            nx = v.x * v.x + v.y * v.y;
        }
        nx += __shfl_xor_sync(FULLM, nx, 4);
        nx += __shfl_xor_sync(FULLM, nx, 2);
        nx += __shfl_xor_sync(FULLM, nx, 1);
        if (lane == 0) na_sm[w] = nx;
    }

    // ---- q for all 8 rows, THIS thread's 8 dims, packed -2*q: 32 ull ----
    ull q2[G_ROWS][4];
#pragma unroll
    for (int r = 0; r < G_ROWS; r++) {
        int si = idxp[rowbase + r];
        const float4* qp = reinterpret_cast<const float4*>(
            emb + (size_t)si * E_DIM + 8 * hf);
        float4 v0 = qp[0], v1 = qp[1];
        q2[r][0] = pk2(-2.f * v0.x, -2.f * v0.y);
        q2[r][1] = pk2(-2.f * v0.z, -2.f * v0.w);
        q2[r][2] = pk2(-2.f * v1.x, -2.f * v1.y);
        q2[r][3] = pk2(-2.f * v1.z, -2.f * v1.w);
    }
    __syncthreads();
    const int selfi = self_sm[w];

    const int halfn  = (n + SPLITS - 1) / SPLITS;   // 25000
    const int jbeg   = split * halfn;
    const int jend   = min(n, jbeg + halfn);
    const int ntiles = (jend - jbeg + TILE - 1) / TILE;

    // ---- top-k state (lanes 0..19 ascending) ----
    float kval   = finf();
    int   kidx   = -1;
    float thresh = finf();

    auto insert = [&](float bv, int bj) {
        float pv = __shfl_up_sync(FULLM, kval, 1);
        int   pj = __shfl_up_sync(FULLM, kidx, 1);
        if (lane < KSEL && bv < kval) {
            if (lane == 0 || bv >= pv) { kval = bv; kidx = bj; }
            else                        { kval = pv; kidx = pj; }
        }
        thresh = __shfl_sync(FULLM, kval, KSEL - 1);
    };

    // ---- phase B: warp w sums halves of row w, scans 128 cands ----
    auto phaseB = [&](int t) {
        const int buf  = t & 1;
        const int base = jbeg + t * TILE;
        const float4* p0 = reinterpret_cast<const float4*>(&sbuf[buf][0][w * RSTRIDE]);
        const float4* p1 = reinterpret_cast<const float4*>(&sbuf[buf][1][w * RSTRIDE]);
        float4 a = p0[lane];
        float4 b = p1[lane];
        float v[4] = {a.x + b.x, a.y + b.y, a.z + b.z, a.w + b.w};
        unsigned hm = 0;
#pragma unroll
        for (int i = 0; i < 4; i++) {
            int j = base + 4 * lane + i;
            if (v[i] < thresh && j != selfi) hm |= (1u << i);
        }
        unsigned red = __reduce_or_sync(FULLM, hm);
        while (red) {
            int i = __ffs(red) - 1; red &= red - 1;
            unsigned m = __ballot_sync(FULLM, (hm >> i) & 1u);
            float vi = v[i];
            int   ji = base + 4 * lane + i;
            while (m) {
                int src = __ffs(m) - 1; m &= m - 1;
                float bv = __shfl_sync(FULLM, vi, src);
                int   bj = __shfl_sync(FULLM, ji, src);
                if (bv < thresh) insert(bv, bj);
            }
        }
    };

    // ---- main loop (lane-contiguous loads: byte addr = tilebase*64 + tid*32) ----
    ull e[4];
    bool vld;
    {
        int j = jbeg + cand;
        vld = (j < jend);
        if (vld) {
            const ulonglong2* p = reinterpret_cast<const ulonglong2*>(
                emb + (size_t)j * E_DIM + 8 * hf);
            ulonglong2 x = p[0], y = p[1];
            e[0] = x.x; e[1] = x.y; e[2] = y.x; e[3] = y.y;
        }
    }

    for (int t = 0; t < ntiles; t++) {
        const int buf = t & 1;
        // partial s = half-norm + half-dot for all 8 rows
        ull nA = fma2(e[0], e[0], 0), nB = fma2(e[1], e[1], 0);
        nA = fma2(e[2], e[2], nA);     nB = fma2(e[3], e[3], nB);
        ull nrm = add2(nA, nB);
        ull acc[G_ROWS];
#pragma unroll
        for (int r = 0; r < G_ROWS; r++) acc[r] = nrm;
#pragma unroll
        for (int k = 0; k < 4; k++) {
            ull ek = e[k];
#pragma unroll
            for (int r = 0; r < G_ROWS; r++)
                acc[r] = fma2(q2[r][k], ek, acc[r]);
        }
#pragma unroll
        for (int r = 0; r < G_ROWS; r++) {
            float lo, hi; upk2(acc[r], lo, hi);
            sbuf[buf][hf][r * RSTRIDE + cand] = vld ? (lo + hi) : BIGV;
        }
        // prefetch next tile (covered by barrier + phaseB)
        if (t + 1 < ntiles) {
            int j = jbeg + (t + 1) * TILE + cand;
            vld = (j < jend);
            if (vld) {
                const ulonglong2* p = reinterpret_cast<const ulonglong2*>(
                    emb + (size_t)j * E_DIM + 8 * hf);
                ulonglong2 x = p[0], y = p[1];
                e[0] = x.x; e[1] = x.y; e[2] = y.x; e[3] = y.y;
            }
        }
        __syncthreads();
        phaseB(t);
    }

    // ---- split rendezvous (2 partials) ----
    if (lane < KSEL) {
        g_pval[set][grp][split][w][lane] = kval;
        g_pidx[set][grp][split][w][lane] = kidx;
    }
    __threadfence();
    __syncthreads();
    if (tid == 0) smflag[0] = atomicAdd(&g_flag[set][grp], 1);
    __syncthreads();

    if (smflag[0] == SPLITS - 1) {      // last arrival merges + features
        __threadfence();
#pragma unroll 1
        for (int s2 = 0; s2 < SPLITS; s2++) {
            if (s2 == split) continue;
            for (int i = 0; i < KSEL; i++) {
                float bv = g_pval[set][grp][s2][w][i];
                int   bj = g_pidx[set][grp][s2][w][i];
                if (bv < thresh) insert(bv, bj);
            }
        }
        const int row = rowbase + w;
        const float na = na_sm[w];
        float wgt = 0.f, sel = 0.f;
        if (lane < KSEL) {
            float d2  = fmaxf(kval + na, 0.f);
            float sim = sqrtf(d2) + 0.001f;
            wgt = __expf(-sim);
            sel = rctx[(size_t)row * n + kidx];
        }
        float sw = wgt, ssw = sel * wgt, ss = sel, ss2 = sel * sel;
#pragma unroll
        for (int off = 16; off; off >>= 1) {
            sw  += __shfl_xor_sync(FULLM, sw,  off);
            ssw += __shfl_xor_sync(FULLM, ssw, off);
            ss  += __shfl_xor_sync(FULLM, ss,  off);
            ss2 += __shfl_xor_sync(FULLM, ss2, off);
        }
        if (lane == 0) {
            g_feats[row][0 + set] = sw;
            g_feats[row][2 + set] = ssw / sw;
            float var = (ss2 - ss * ss / (float)KSEL) / (float)(KSEL - 1);
            g_feats[row][4 + set] = sqrtf(fmaxf(var, 0.f));
        }
        if (tid == 0) g_flag[set][grp] = 0;
    }

    // ---- global tail: MLP ----
    __threadfence();
    __syncthreads();
    if (tid == 0) smflag[1] = atomicAdd(&g_done, 1);
    __syncthreads();
    if (smflag[1] != NBLK - 1) return;
    __threadfence();

#pragma unroll
    for (int rr = 0; rr < 2; rr++) {
        int r = tid + BTHR * rr;
        float f[8];
#pragma unroll
        for (int i = 0; i < 6; i++) f[i] = g_feats[r][i];
        f[6] = mean_in[r];
        f[7] = std_in[r];
        float m = bm[0], sd = bs[0];
#pragma unroll 4
        for (int jj = 0; jj < HID; jj++) {
            float h = b1[jj];
#pragma unroll
            for (int i = 0; i < 8; i++) h = fmaf(f[i], W1[i * HID + jj], h);
            h = fmaxf(h, 0.f);
            m  = fmaf(h, Wm[jj], m);
            sd = fmaf(h, Ws[jj], sd);
        }
        out[r]          = m;
        out[B_ROWS + r] = sd;
    }
    if (tid == 0) g_done = 0;
}

// ---------------------------------------------------------------------------
extern "C" void kernel_launch(void* const* d_in, const int* in_sizes, int n_in,
                              void* d_out, int out_size) {
    const float* emb0    = (const float*)d_in[0];
    const float* emb1    = (const float*)d_in[1];
    const float* rctx0   = (const float*)d_in[2];
    const float* rctx1   = (const float*)d_in[3];
    const int*   idx0    = (const int*)  d_in[4];
    const int*   idx1    = (const int*)  d_in[5];
    const float* mean_in = (const float*)d_in[6];
    const float* std_in  = (const float*)d_in[7];
    const float* W1      = (const float*)d_in[8];
    const float* b1      = (const float*)d_in[9];
    const float* Wm      = (const float*)d_in[10];
    const float* bm      = (const float*)d_in[11];
    const float* Ws      = (const float*)d_in[12];
    const float* bs      = (const float*)d_in[13];

    int n = in_sizes[0] / E_DIM;    // 50000

    dim3 grid(NGRP, 2, SPLITS);
    knn_kernel<<<grid, BTHR>>>(emb0, emb1, rctx0, rctx1, idx0, idx1,
                               mean_in, std_in, W1, b1, Wm, bm, Ws, bs,
                               (float*)d_out, n);
}